// round 12
// baseline (speedup 1.0000x reference)
#include <cuda_runtime.h>
#include <cuda_fp16.h>
#include <cuda_bf16.h>
#include <cstdint>

#define MAX_N 100000
#define MAX_E 3200000
#define D 128
#define CAP 128   // fixed CSR bucket capacity per node (deg ~ Poisson(32))
#define SMS 136   // gemm smem row stride in halves

// Scratch
__device__ __half g_hs[(size_t)MAX_N * D];   // x@W1 (fp16), unscaled
__device__ float  g_h[(size_t)MAX_N * D];    // hidden after leaky (for pooling)
__device__ float  g_ss[MAX_N];               // dinv * (h @ W2)
__device__ float  g_dinv[MAX_N];
__device__ int    g_deg[MAX_N];
__device__ int    g_cur[MAX_N];              // scatter cursor (base = i*CAP)
__device__ int    g_csr[(size_t)MAX_N * CAP];// src ids, fixed buckets per dst
__device__ float  g_pool[64 * D];            // per-graph feature sums
__device__ int    g_gcount[64];              // nodes per graph

// ---------------------------------------------------------------------------
__global__ void k_zero(int N) {
    int i = blockIdx.x * blockDim.x + threadIdx.x;
    if (i < N) g_cur[i] = i * CAP;
    if (i < 64 * D) g_pool[i] = 0.f;
    if (i < 64) g_gcount[i] = 0;
}

__global__ void k_scatter(const int* __restrict__ ei, int E) {
    int e = blockIdx.x * blockDim.x + threadIdx.x;
    if (e >= E) return;
    int src = __ldg(ei + e);
    int dst = __ldg(ei + E + e);
    int pos = atomicAdd(&g_cur[dst], 1);
    g_csr[pos] = src;
}

__global__ void k_dinv(int N) {
    int i = blockIdx.x * blockDim.x + threadIdx.x;
    if (i >= N) return;
    int d = g_cur[i] - i * CAP;
    g_deg[i] = d;
    g_dinv[i] = rsqrtf((float)d + 1.0f);
}

// ---------------------------------------------------------------------------
// Tensor-core GEMM: g_hs = fp16( (x @ W1)[row] ), unscaled.
// ---------------------------------------------------------------------------
__global__ void __launch_bounds__(256) k_gemm_tc(const float* __restrict__ x,
                                                 const float* __restrict__ W, int N) {
    extern __shared__ __half sh[];
    __half* xh = sh;               // [128][SMS]
    __half* wt = sh + 128 * SMS;   // [128][SMS] W transposed (n, k)
    int tid = threadIdx.x;
    int row0 = blockIdx.x * 128;

    const float4* x4 = (const float4*)x;
    #pragma unroll 4
    for (int i = tid; i < 4096; i += 256) {
        int r = i >> 5, c = (i & 31) * 4;
        float4 v = make_float4(0.f, 0.f, 0.f, 0.f);
        if (row0 + r < N) v = __ldg(x4 + (size_t)(row0 + r) * 32 + (c >> 2));
        __half2* p = (__half2*)&xh[r * SMS + c];
        p[0] = __floats2half2_rn(v.x, v.y);
        p[1] = __floats2half2_rn(v.z, v.w);
    }
    #pragma unroll 4
    for (int i = tid; i < 16384; i += 256) {
        int k = i >> 7, n = i & 127;
        wt[n * SMS + k] = __float2half_rn(__ldg(W + i));
    }
    __syncthreads();

    int wid = tid >> 5;
    int lane = tid & 31;
    int gid = lane >> 2;
    int tig = lane & 3;
    int wr0 = wid * 16;

    float acc[16][4];
    #pragma unroll
    for (int ng = 0; ng < 16; ng++)
        #pragma unroll
        for (int q = 0; q < 4; q++) acc[ng][q] = 0.f;

    const __half* arow_lo = xh + (wr0 + gid) * SMS;
    const __half* arow_hi = xh + (wr0 + gid + 8) * SMS;

    #pragma unroll
    for (int kc = 0; kc < 8; kc++) {
        int k0 = kc * 16;
        uint32_t a0 = *(const uint32_t*)(arow_lo + k0 + 2 * tig);
        uint32_t a1 = *(const uint32_t*)(arow_hi + k0 + 2 * tig);
        uint32_t a2 = *(const uint32_t*)(arow_lo + k0 + 2 * tig + 8);
        uint32_t a3 = *(const uint32_t*)(arow_hi + k0 + 2 * tig + 8);
        #pragma unroll
        for (int ng = 0; ng < 16; ng++) {
            const __half* brow = wt + (ng * 8 + gid) * SMS;
            uint32_t b0 = *(const uint32_t*)(brow + k0 + 2 * tig);
            uint32_t b1 = *(const uint32_t*)(brow + k0 + 2 * tig + 8);
            asm volatile(
                "mma.sync.aligned.m16n8k16.row.col.f32.f16.f16.f32 "
                "{%0,%1,%2,%3}, {%4,%5,%6,%7}, {%8,%9}, {%0,%1,%2,%3};"
                : "+f"(acc[ng][0]), "+f"(acc[ng][1]),
                  "+f"(acc[ng][2]), "+f"(acc[ng][3])
                : "r"(a0), "r"(a1), "r"(a2), "r"(a3), "r"(b0), "r"(b1));
        }
    }

    int r_lo = row0 + wr0 + gid;
    int r_hi = r_lo + 8;
    __half2* o_lo = (__half2*)(g_hs + (size_t)r_lo * D);
    __half2* o_hi = (__half2*)(g_hs + (size_t)r_hi * D);
    #pragma unroll
    for (int ng = 0; ng < 16; ng++) {
        int c = ng * 8 + 2 * tig;
        if (r_lo < N) o_lo[c >> 1] = __floats2half2_rn(acc[ng][0], acc[ng][1]);
        if (r_hi < N) o_hi[c >> 1] = __floats2half2_rn(acc[ng][2], acc[ng][3]);
    }
}

// ---------------------------------------------------------------------------
// Node aggregation: one warp per node, TWO edges per gather instruction.
// Lane layout: half = lane>>4 selects edge of a pair; hl = lane&15 selects
// the 16B (8-feature) chunk of the 256B row. acc[8] per lane in fp32.
// h_i = leaky( dinv_i * (Σ dinv_s*hs_s + dinv_i*hs_i) + b1 ); ss_i = dinv_i*(h_i@W2)
// ---------------------------------------------------------------------------
__global__ void __launch_bounds__(256) k_node_agg(const float* __restrict__ b1,
                                                  const float* __restrict__ W2, int N) {
    int g = blockIdx.x * blockDim.x + threadIdx.x;
    int i = g >> 5;
    int lane = g & 31;
    if (i >= N) return;
    int cnt = g_deg[i];
    float di = g_dinv[i];
    const int* csr = g_csr + (size_t)i * CAP;
    int half = lane >> 4;
    int hl = lane & 15;
    const uint4* hs4 = (const uint4*)g_hs;   // 16 uint4 per row

    float acc[8];
    #pragma unroll
    for (int f = 0; f < 8; f++) acc[f] = 0.f;

    int j = 0;
    for (; j + 8 <= cnt; j += 8) {
        int s = 0;
        if (lane < 8) s = __ldg(csr + j + lane);
        #pragma unroll
        for (int q = 0; q < 4; q++) {
            int se = __shfl_sync(0xffffffffu, s, q * 2 + half);
            float ds = __ldg(g_dinv + se);
            uint4 rv = __ldg(hs4 + (size_t)se * 16 + hl);
            float2 f0 = __half22float2(*(const __half2*)&rv.x);
            float2 f1 = __half22float2(*(const __half2*)&rv.y);
            float2 f2 = __half22float2(*(const __half2*)&rv.z);
            float2 f3 = __half22float2(*(const __half2*)&rv.w);
            acc[0] = fmaf(ds, f0.x, acc[0]); acc[1] = fmaf(ds, f0.y, acc[1]);
            acc[2] = fmaf(ds, f1.x, acc[2]); acc[3] = fmaf(ds, f1.y, acc[3]);
            acc[4] = fmaf(ds, f2.x, acc[4]); acc[5] = fmaf(ds, f2.y, acc[5]);
            acc[6] = fmaf(ds, f3.x, acc[6]); acc[7] = fmaf(ds, f3.y, acc[7]);
        }
    }
    for (; j < cnt; j += 2) {
        int s0 = __ldg(csr + j);
        int s1 = (j + 1 < cnt) ? __ldg(csr + j + 1) : s0;
        int se = half ? s1 : s0;
        float ds = __ldg(g_dinv + se);
        if (half && j + 1 >= cnt) ds = 0.f;
        uint4 rv = __ldg(hs4 + (size_t)se * 16 + hl);
        float2 f0 = __half22float2(*(const __half2*)&rv.x);
        float2 f1 = __half22float2(*(const __half2*)&rv.y);
        float2 f2 = __half22float2(*(const __half2*)&rv.z);
        float2 f3 = __half22float2(*(const __half2*)&rv.w);
        acc[0] = fmaf(ds, f0.x, acc[0]); acc[1] = fmaf(ds, f0.y, acc[1]);
        acc[2] = fmaf(ds, f1.x, acc[2]); acc[3] = fmaf(ds, f1.y, acc[3]);
        acc[4] = fmaf(ds, f2.x, acc[4]); acc[5] = fmaf(ds, f2.y, acc[5]);
        acc[6] = fmaf(ds, f3.x, acc[6]); acc[7] = fmaf(ds, f3.y, acc[7]);
    }

    // Combine the two half-warps (both end up with the full sum).
    #pragma unroll
    for (int f = 0; f < 8; f++) acc[f] += __shfl_xor_sync(0xffffffffu, acc[f], 16);

    // Self term: + dinv_i * hs[i]
    {
        uint4 rv = __ldg(hs4 + (size_t)i * 16 + hl);
        float2 f0 = __half22float2(*(const __half2*)&rv.x);
        float2 f1 = __half22float2(*(const __half2*)&rv.y);
        float2 f2 = __half22float2(*(const __half2*)&rv.z);
        float2 f3 = __half22float2(*(const __half2*)&rv.w);
        acc[0] = fmaf(di, f0.x, acc[0]); acc[1] = fmaf(di, f0.y, acc[1]);
        acc[2] = fmaf(di, f1.x, acc[2]); acc[3] = fmaf(di, f1.y, acc[3]);
        acc[4] = fmaf(di, f2.x, acc[4]); acc[5] = fmaf(di, f2.y, acc[5]);
        acc[6] = fmaf(di, f3.x, acc[6]); acc[7] = fmaf(di, f3.y, acc[7]);
    }

    // bias + leaky
    float4 bA = __ldg(((const float4*)b1) + hl * 2);
    float4 bB = __ldg(((const float4*)b1) + hl * 2 + 1);
    float v[8];
    v[0] = fmaf(di, acc[0], bA.x); v[1] = fmaf(di, acc[1], bA.y);
    v[2] = fmaf(di, acc[2], bA.z); v[3] = fmaf(di, acc[3], bA.w);
    v[4] = fmaf(di, acc[4], bB.x); v[5] = fmaf(di, acc[5], bB.y);
    v[6] = fmaf(di, acc[6], bB.z); v[7] = fmaf(di, acc[7], bB.w);
    #pragma unroll
    for (int f = 0; f < 8; f++) v[f] = v[f] > 0.f ? v[f] : 0.01f * v[f];

    // store h (lanes 0-15 only; halves hold identical data)
    if (!half) {
        float4* o = (float4*)(g_h + (size_t)i * D);
        o[hl * 2]     = make_float4(v[0], v[1], v[2], v[3]);
        o[hl * 2 + 1] = make_float4(v[4], v[5], v[6], v[7]);
    }

    // W2 dot: per-lane partial over 8 features, reduce across 16 lanes.
    float4 wA = __ldg(((const float4*)W2) + hl * 2);
    float4 wB = __ldg(((const float4*)W2) + hl * 2 + 1);
    float p = v[0] * wA.x + v[1] * wA.y + v[2] * wA.z + v[3] * wA.w
            + v[4] * wB.x + v[5] * wB.y + v[6] * wB.z + v[7] * wB.w;
    #pragma unroll
    for (int off = 8; off; off >>= 1) p += __shfl_xor_sync(0xffffffffu, p, off);
    if (lane == 0) g_ss[i] = di * p;
}

// ---------------------------------------------------------------------------
// Leaf head: out[i] = dinv[i] * (Σ_nbr ss[src] + ss[i]) + b2
// ---------------------------------------------------------------------------
__global__ void k_leaf(const float* __restrict__ b2, float* __restrict__ out, int N) {
    int i = blockIdx.x * blockDim.x + threadIdx.x;
    if (i >= N) return;
    int cnt = g_deg[i];
    const int* csr = g_csr + (size_t)i * CAP;
    float sum = g_ss[i];
    int j = 0;
    for (; j + 8 <= cnt; j += 8) {
        int src[8];
        #pragma unroll
        for (int u = 0; u < 8; u++) src[u] = __ldg(csr + j + u);
        float sv[8];
        #pragma unroll
        for (int u = 0; u < 8; u++) sv[u] = __ldg(g_ss + src[u]);
        #pragma unroll
        for (int u = 0; u < 8; u++) sum += sv[u];
    }
    for (; j < cnt; j++) sum += __ldg(g_ss + __ldg(csr + j));
    out[i] = fmaf(g_dinv[i], sum, __ldg(b2));
}

// ---------------------------------------------------------------------------
__global__ void k_pool(const int* __restrict__ batch, int N) {
    int t = threadIdx.x;
    int n0 = blockIdx.x * 256;
    int n1 = min(n0 + 256, N);
    if (n0 >= N) return;
    int cur = __ldg(batch + n0);
    int runStart = n0;
    float sum = 0.f;
    for (int n = n0; n < n1; n++) {
        int bg = __ldg(batch + n);
        if (bg != cur) {
            atomicAdd(&g_pool[cur * D + t], sum);
            if (t == 0) atomicAdd(&g_gcount[cur], n - runStart);
            sum = 0.f; cur = bg; runStart = n;
        }
        sum += g_h[(size_t)n * D + t];
    }
    atomicAdd(&g_pool[cur * D + t], sum);
    if (t == 0) atomicAdd(&g_gcount[cur], n1 - runStart);
}

__global__ void k_eos(const float* __restrict__ W3, const float* __restrict__ b3,
                      float* __restrict__ out_eos) {
    int gph = blockIdx.x;
    int t = threadIdx.x;
    int cnt = g_gcount[gph];
    float denom = (float)(cnt > 0 ? cnt : 1);
    float val = (g_pool[gph * D + t] / denom) * __ldg(W3 + t);
    __shared__ float red[128];
    red[t] = val;
    __syncthreads();
    #pragma unroll
    for (int st = 64; st > 0; st >>= 1) {
        if (t < st) red[t] += red[t + st];
        __syncthreads();
    }
    if (t == 0) out_eos[gph] = red[0] + __ldg(b3);
}

// ---------------------------------------------------------------------------
extern "C" void kernel_launch(void* const* d_in, const int* in_sizes, int n_in,
                              void* d_out, int out_size) {
    const float* x     = (const float*)d_in[0];
    const int*   ei    = (const int*)d_in[1];
    const int*   batch = (const int*)d_in[2];
    const float* W1    = (const float*)d_in[3];
    const float* b1    = (const float*)d_in[4];
    const float* W2    = (const float*)d_in[5];
    const float* b2    = (const float*)d_in[6];
    const float* W3    = (const float*)d_in[7];
    const float* b3    = (const float*)d_in[8];
    float* out = (float*)d_out;

    int N = in_sizes[0] / D;
    int E = in_sizes[1] / 2;
    int G = out_size - N;

    int smem = 2 * 128 * SMS * (int)sizeof(__half);  // 69632B
    cudaFuncSetAttribute(k_gemm_tc, cudaFuncAttributeMaxDynamicSharedMemorySize, smem);

    static cudaStream_t s2 = nullptr;
    static cudaEvent_t eFork = nullptr, eJoin = nullptr, eAgg = nullptr, eTail = nullptr;
    if (!s2) {
        cudaStreamCreateWithFlags(&s2, cudaStreamNonBlocking);
        cudaEventCreateWithFlags(&eFork, cudaEventDisableTiming);
        cudaEventCreateWithFlags(&eJoin, cudaEventDisableTiming);
        cudaEventCreateWithFlags(&eAgg, cudaEventDisableTiming);
        cudaEventCreateWithFlags(&eTail, cudaEventDisableTiming);
    }

    // Fork: s2 runs zero -> scatter -> dinv (graph side); main runs gemm.
    cudaEventRecord(eFork, 0);
    cudaStreamWaitEvent(s2, eFork, 0);
    k_zero<<<(N + 255) / 256, 256, 0, s2>>>(N);
    k_gemm_tc<<<(N + 127) / 128, 256, smem>>>(x, W1, N);
    k_scatter<<<(E + 255) / 256, 256, 0, s2>>>(ei, E);
    k_dinv<<<(N + 255) / 256, 256, 0, s2>>>(N);
    cudaEventRecord(eJoin, s2);
    cudaStreamWaitEvent(0, eJoin, 0);

    k_node_agg<<<(N + 7) / 8, 256>>>(b1, W2, N);
    cudaEventRecord(eAgg, 0);

    // Tail fork: pool+eos on s2, leaf on main.
    cudaStreamWaitEvent(s2, eAgg, 0);
    k_pool<<<(N + 255) / 256, 128, 0, s2>>>(batch, N);
    k_eos<<<G, 128, 0, s2>>>(W3, b3, out + N);
    cudaEventRecord(eTail, s2);

    k_leaf<<<(N + 255) / 256, 256>>>(b2, out, N);
    cudaStreamWaitEvent(0, eTail, 0);
}

// round 13
// speedup vs baseline: 1.0126x; 1.0126x over previous
#include <cuda_runtime.h>
#include <cuda_fp16.h>
#include <cuda_bf16.h>
#include <cstdint>

#define MAX_N 100000
#define MAX_E 3200000
#define D 128
#define CAP 128   // fixed CSR bucket capacity per node (deg ~ Poisson(32))
#define SMS 136   // gemm smem row stride in halves

// Scratch. NOTE: g_cur/g_pool/g_gcount rely on module-load zero-init for the
// first call; k_reset restores the zeroed state at the end of every call.
__device__ __half g_hs[(size_t)MAX_N * D];   // x@W1 (fp16), scaled by dinv in k_dinv_scale
__device__ float  g_h[(size_t)MAX_N * D];    // hidden after leaky (for pooling)
__device__ float  g_ss[MAX_N];               // dinv * (h @ W2)
__device__ float  g_dinv[MAX_N];
__device__ int    g_deg[MAX_N];
__device__ int    g_cur[MAX_N];              // per-node scatter counter (starts at 0)
__device__ int    g_csr[(size_t)MAX_N * CAP];// src ids, fixed buckets per dst
__device__ float  g_pool[64 * D];            // per-graph feature sums (starts 0)
__device__ int    g_gcount[64];              // nodes per graph (starts 0)

// ---------------------------------------------------------------------------
__global__ void k_scatter(const int* __restrict__ ei, int E) {
    int e = blockIdx.x * blockDim.x + threadIdx.x;
    if (e >= E) return;
    int src = __ldg(ei + e);
    int dst = __ldg(ei + E + e);
    int pos = dst * CAP + atomicAdd(&g_cur[dst], 1);
    g_csr[pos] = src;
}

// Trailing reset: restore zeroed state for the next call. Runs overlapped
// with the tail (after pool/eos consumed g_pool/g_gcount; leaf uses only
// g_deg/g_dinv/g_ss, so zeroing g_cur concurrently is safe).
__global__ void k_reset(int N) {
    int i = blockIdx.x * blockDim.x + threadIdx.x;
    if (i < N) g_cur[i] = 0;
    if (i < 64 * D) g_pool[i] = 0.f;
    if (i < 64) g_gcount[i] = 0;
}

// ---------------------------------------------------------------------------
// Tensor-core GEMM: g_hs = fp16( (x @ W1)[row] ), unscaled.
// ---------------------------------------------------------------------------
__global__ void __launch_bounds__(256) k_gemm_tc(const float* __restrict__ x,
                                                 const float* __restrict__ W, int N) {
    extern __shared__ __half sh[];
    __half* xh = sh;               // [128][SMS]
    __half* wt = sh + 128 * SMS;   // [128][SMS] W transposed (n, k)
    int tid = threadIdx.x;
    int row0 = blockIdx.x * 128;

    const float4* x4 = (const float4*)x;
    #pragma unroll 4
    for (int i = tid; i < 4096; i += 256) {
        int r = i >> 5, c = (i & 31) * 4;
        float4 v = make_float4(0.f, 0.f, 0.f, 0.f);
        if (row0 + r < N) v = __ldg(x4 + (size_t)(row0 + r) * 32 + (c >> 2));
        __half2* p = (__half2*)&xh[r * SMS + c];
        p[0] = __floats2half2_rn(v.x, v.y);
        p[1] = __floats2half2_rn(v.z, v.w);
    }
    #pragma unroll 4
    for (int i = tid; i < 16384; i += 256) {
        int k = i >> 7, n = i & 127;
        wt[n * SMS + k] = __float2half_rn(__ldg(W + i));
    }
    __syncthreads();

    int wid = tid >> 5;
    int lane = tid & 31;
    int gid = lane >> 2;
    int tig = lane & 3;
    int wr0 = wid * 16;

    float acc[16][4];
    #pragma unroll
    for (int ng = 0; ng < 16; ng++)
        #pragma unroll
        for (int q = 0; q < 4; q++) acc[ng][q] = 0.f;

    const __half* arow_lo = xh + (wr0 + gid) * SMS;
    const __half* arow_hi = xh + (wr0 + gid + 8) * SMS;

    #pragma unroll
    for (int kc = 0; kc < 8; kc++) {
        int k0 = kc * 16;
        uint32_t a0 = *(const uint32_t*)(arow_lo + k0 + 2 * tig);
        uint32_t a1 = *(const uint32_t*)(arow_hi + k0 + 2 * tig);
        uint32_t a2 = *(const uint32_t*)(arow_lo + k0 + 2 * tig + 8);
        uint32_t a3 = *(const uint32_t*)(arow_hi + k0 + 2 * tig + 8);
        #pragma unroll
        for (int ng = 0; ng < 16; ng++) {
            const __half* brow = wt + (ng * 8 + gid) * SMS;
            uint32_t b0 = *(const uint32_t*)(brow + k0 + 2 * tig);
            uint32_t b1 = *(const uint32_t*)(brow + k0 + 2 * tig + 8);
            asm volatile(
                "mma.sync.aligned.m16n8k16.row.col.f32.f16.f16.f32 "
                "{%0,%1,%2,%3}, {%4,%5,%6,%7}, {%8,%9}, {%0,%1,%2,%3};"
                : "+f"(acc[ng][0]), "+f"(acc[ng][1]),
                  "+f"(acc[ng][2]), "+f"(acc[ng][3])
                : "r"(a0), "r"(a1), "r"(a2), "r"(a3), "r"(b0), "r"(b1));
        }
    }

    int r_lo = row0 + wr0 + gid;
    int r_hi = r_lo + 8;
    __half2* o_lo = (__half2*)(g_hs + (size_t)r_lo * D);
    __half2* o_hi = (__half2*)(g_hs + (size_t)r_hi * D);
    #pragma unroll
    for (int ng = 0; ng < 16; ng++) {
        int c = ng * 8 + 2 * tig;
        if (r_lo < N) o_lo[c >> 1] = __floats2half2_rn(acc[ng][0], acc[ng][1]);
        if (r_hi < N) o_hi[c >> 1] = __floats2half2_rn(acc[ng][2], acc[ng][3]);
    }
}

// ---------------------------------------------------------------------------
// dinv/deg from final cursors + in-place scale of hs by dinv. One warp/node.
// ---------------------------------------------------------------------------
__global__ void k_dinv_scale(int N) {
    int g = blockIdx.x * blockDim.x + threadIdx.x;
    int i = g >> 5;
    int lane = g & 31;
    if (i >= N) return;
    int d = g_cur[i];
    float di = rsqrtf((float)d + 1.0f);
    if (lane == 0) { g_dinv[i] = di; g_deg[i] = d; }
    uint2* p = (uint2*)(g_hs + (size_t)i * D) + lane;
    uint2 v = *p;
    float2 f0 = __half22float2(*(__half2*)&v.x);
    float2 f1 = __half22float2(*(__half2*)&v.y);
    *(__half2*)&v.x = __floats2half2_rn(di * f0.x, di * f0.y);
    *(__half2*)&v.y = __floats2half2_rn(di * f1.x, di * f1.y);
    *p = v;
}

// ---------------------------------------------------------------------------
// Node aggregation + bias + leaky + h@W2. One warp per node, 8-deep pipeline.
// h_i = leaky( dinv[i]*(Σ_nbr hs[src] + hs[i]) + b1 );  ss_i = dinv[i]*(h_i@W2)
// ---------------------------------------------------------------------------
__global__ void __launch_bounds__(256) k_node_agg(const float* __restrict__ b1,
                                                  const float* __restrict__ W2, int N) {
    int g = blockIdx.x * blockDim.x + threadIdx.x;
    int i = g >> 5;
    int lane = g & 31;
    if (i >= N) return;
    int cnt = g_deg[i];
    const int* csr = g_csr + (size_t)i * CAP;
    const uint2* hs2 = (const uint2*)g_hs;

    float4 acc = make_float4(0.f, 0.f, 0.f, 0.f);
    {
        uint2 rv = __ldg(hs2 + (size_t)i * 32 + lane);
        float2 f0 = __half22float2(*(const __half2*)&rv.x);
        float2 f1 = __half22float2(*(const __half2*)&rv.y);
        acc.x += f0.x; acc.y += f0.y; acc.z += f1.x; acc.w += f1.y;
    }
    int j = 0;
    for (; j + 8 <= cnt; j += 8) {
        int src[8];
        #pragma unroll
        for (int u = 0; u < 8; u++) src[u] = __ldg(csr + j + u);
        uint2 rv[8];
        #pragma unroll
        for (int u = 0; u < 8; u++) rv[u] = __ldg(hs2 + (size_t)src[u] * 32 + lane);
        #pragma unroll
        for (int u = 0; u < 8; u++) {
            float2 f0 = __half22float2(*(const __half2*)&rv[u].x);
            float2 f1 = __half22float2(*(const __half2*)&rv[u].y);
            acc.x += f0.x; acc.y += f0.y; acc.z += f1.x; acc.w += f1.y;
        }
    }
    for (; j < cnt; j++) {
        int src = __ldg(csr + j);
        uint2 rv = __ldg(hs2 + (size_t)src * 32 + lane);
        float2 f0 = __half22float2(*(const __half2*)&rv.x);
        float2 f1 = __half22float2(*(const __half2*)&rv.y);
        acc.x += f0.x; acc.y += f0.y; acc.z += f1.x; acc.w += f1.y;
    }

    float di = g_dinv[i];
    float4 b = __ldg(((const float4*)b1) + lane);
    float4 v;
    v.x = fmaf(di, acc.x, b.x);
    v.y = fmaf(di, acc.y, b.y);
    v.z = fmaf(di, acc.z, b.z);
    v.w = fmaf(di, acc.w, b.w);
    v.x = v.x > 0.f ? v.x : 0.01f * v.x;
    v.y = v.y > 0.f ? v.y : 0.01f * v.y;
    v.z = v.z > 0.f ? v.z : 0.01f * v.z;
    v.w = v.w > 0.f ? v.w : 0.01f * v.w;
    ((float4*)g_h)[(size_t)i * 32 + lane] = v;

    float4 w = __ldg(((const float4*)W2) + lane);
    float p = v.x * w.x + v.y * w.y + v.z * w.z + v.w * w.w;
    #pragma unroll
    for (int off = 16; off; off >>= 1) p += __shfl_xor_sync(0xffffffffu, p, off);
    if (lane == 0) g_ss[i] = di * p;
}

// ---------------------------------------------------------------------------
// Leaf head: out[i] = dinv[i] * (Σ_nbr ss[src] + ss[i]) + b2
// ---------------------------------------------------------------------------
__global__ void k_leaf(const float* __restrict__ b2, float* __restrict__ out, int N) {
    int i = blockIdx.x * blockDim.x + threadIdx.x;
    if (i >= N) return;
    int cnt = g_deg[i];
    const int* csr = g_csr + (size_t)i * CAP;
    float sum = g_ss[i];
    int j = 0;
    for (; j + 8 <= cnt; j += 8) {
        int src[8];
        #pragma unroll
        for (int u = 0; u < 8; u++) src[u] = __ldg(csr + j + u);
        float sv[8];
        #pragma unroll
        for (int u = 0; u < 8; u++) sv[u] = __ldg(g_ss + src[u]);
        #pragma unroll
        for (int u = 0; u < 8; u++) sum += sv[u];
    }
    for (; j < cnt; j++) sum += __ldg(g_ss + __ldg(csr + j));
    out[i] = fmaf(g_dinv[i], sum, __ldg(b2));
}

// ---------------------------------------------------------------------------
__global__ void k_pool(const int* __restrict__ batch, int N) {
    int t = threadIdx.x;
    int n0 = blockIdx.x * 256;
    int n1 = min(n0 + 256, N);
    if (n0 >= N) return;
    int cur = __ldg(batch + n0);
    int runStart = n0;
    float sum = 0.f;
    for (int n = n0; n < n1; n++) {
        int bg = __ldg(batch + n);
        if (bg != cur) {
            atomicAdd(&g_pool[cur * D + t], sum);
            if (t == 0) atomicAdd(&g_gcount[cur], n - runStart);
            sum = 0.f; cur = bg; runStart = n;
        }
        sum += g_h[(size_t)n * D + t];
    }
    atomicAdd(&g_pool[cur * D + t], sum);
    if (t == 0) atomicAdd(&g_gcount[cur], n1 - runStart);
}

__global__ void k_eos(const float* __restrict__ W3, const float* __restrict__ b3,
                      float* __restrict__ out_eos) {
    int gph = blockIdx.x;
    int t = threadIdx.x;
    int cnt = g_gcount[gph];
    float denom = (float)(cnt > 0 ? cnt : 1);
    float val = (g_pool[gph * D + t] / denom) * __ldg(W3 + t);
    __shared__ float red[128];
    red[t] = val;
    __syncthreads();
    #pragma unroll
    for (int st = 64; st > 0; st >>= 1) {
        if (t < st) red[t] += red[t + st];
        __syncthreads();
    }
    if (t == 0) out_eos[gph] = red[0] + __ldg(b3);
}

// ---------------------------------------------------------------------------
extern "C" void kernel_launch(void* const* d_in, const int* in_sizes, int n_in,
                              void* d_out, int out_size) {
    const float* x     = (const float*)d_in[0];
    const int*   ei    = (const int*)d_in[1];
    const int*   batch = (const int*)d_in[2];
    const float* W1    = (const float*)d_in[3];
    const float* b1    = (const float*)d_in[4];
    const float* W2    = (const float*)d_in[5];
    const float* b2    = (const float*)d_in[6];
    const float* W3    = (const float*)d_in[7];
    const float* b3    = (const float*)d_in[8];
    float* out = (float*)d_out;

    int N = in_sizes[0] / D;
    int E = in_sizes[1] / 2;
    int G = out_size - N;

    int smem = 2 * 128 * SMS * (int)sizeof(__half);  // 69632B
    cudaFuncSetAttribute(k_gemm_tc, cudaFuncAttributeMaxDynamicSharedMemorySize, smem);

    static cudaStream_t s2 = nullptr;
    static cudaEvent_t eFork = nullptr, eJoin = nullptr, eAgg = nullptr, eTail = nullptr;
    if (!s2) {
        cudaStreamCreateWithFlags(&s2, cudaStreamNonBlocking);
        cudaEventCreateWithFlags(&eFork, cudaEventDisableTiming);
        cudaEventCreateWithFlags(&eJoin, cudaEventDisableTiming);
        cudaEventCreateWithFlags(&eAgg, cudaEventDisableTiming);
        cudaEventCreateWithFlags(&eTail, cudaEventDisableTiming);
    }

    // Fork: main runs gemm; s2 runs scatter (cursors arrive zeroed from the
    // previous call's k_reset / module init).
    cudaEventRecord(eFork, 0);
    cudaStreamWaitEvent(s2, eFork, 0);
    k_gemm_tc<<<(N + 127) / 128, 256, smem>>>(x, W1, N);          // kernel 1
    k_scatter<<<(E + 255) / 256, 256, 0, s2>>>(ei, E);            // kernel 2
    cudaEventRecord(eJoin, s2);
    cudaStreamWaitEvent(0, eJoin, 0);

    k_dinv_scale<<<(N * 32 + 255) / 256, 256>>>(N);               // kernel 3
    k_node_agg<<<(N + 7) / 8, 256>>>(b1, W2, N);                  // kernel 4 <- profiled
    cudaEventRecord(eAgg, 0);

    // Tail fork: pool+eos+reset on s2, leaf on main.
    cudaStreamWaitEvent(s2, eAgg, 0);
    k_pool<<<(N + 255) / 256, 128, 0, s2>>>(batch, N);
    k_eos<<<G, 128, 0, s2>>>(W3, b3, out + N);
    k_reset<<<(N + 255) / 256, 256, 0, s2>>>(N);
    cudaEventRecord(eTail, s2);

    k_leaf<<<(N + 255) / 256, 256>>>(b2, out, N);
    cudaStreamWaitEvent(0, eTail, 0);
}